// round 14
// baseline (speedup 1.0000x reference)
#include <cuda_runtime.h>
#include <cuda_fp16.h>

// SpatialGraphConv fused (fp16 mma.m16n8k16 main GEMM, fp32 accum).
// out[n,o,m] = relu( sum_c W[o,c]*Z[c,m] + bo[o] + g1b[o]*sumAe[m%25] )
//   Z rows 0..63  = x (res branch), rows 64..127 = xA = x@Ae (gcn branch)
// N=64 Cin=64 Cout=128 T=300 V=25, m in [0,7500). Tiles: 125 m-cols x 128 o.
// 296 CTAs x 256 thr (2 CTAs/SM, independent tile pipelines, plain syncthreads).
// Z as half2 image [kw=k/2][m] matching fp16 B-frags; W pre-baked in A-frag
// order (1 LDS.128/frag). Stage-1 xA via tf32 mma on raw fp32. scol bias table.

#define NTILES (64*60)
#define MTOT   7500
#define RS     132      // raw x row stride (floats)
#define ZS     136      // Zh row stride (words; mod 32 == 8 -> conflict-free)
#define AS     40       // Ae row stride

__device__ __align__(16) __half g_Whf[16384];  // fp16 W in m16n8k16 A-frag order
__device__ float g_bo[128];
__device__ float g_g1b[128];
__device__ float g_Ae32[1024];                 // tf32 bits, zero-padded 32x32
__device__ float g_sumAe[32];

static __device__ __forceinline__ void mma_tf32(float* c, const unsigned* a, const unsigned* b) {
    asm volatile(
        "mma.sync.aligned.m16n8k8.row.col.f32.tf32.tf32.f32 "
        "{%0,%1,%2,%3}, {%4,%5,%6,%7}, {%8,%9}, {%0,%1,%2,%3};"
        : "+f"(c[0]), "+f"(c[1]), "+f"(c[2]), "+f"(c[3])
        : "r"(a[0]), "r"(a[1]), "r"(a[2]), "r"(a[3]), "r"(b[0]), "r"(b[1]));
}
static __device__ __forceinline__ void mma_f16(float* c, const unsigned* a,
                                               unsigned b0, unsigned b1) {
    asm volatile(
        "mma.sync.aligned.m16n8k16.row.col.f32.f16.f16.f32 "
        "{%0,%1,%2,%3}, {%4,%5,%6,%7}, {%8,%9}, {%0,%1,%2,%3};"
        : "+f"(c[0]), "+f"(c[1]), "+f"(c[2]), "+f"(c[3])
        : "r"(a[0]), "r"(a[1]), "r"(a[2]), "r"(a[3]), "r"(b0), "r"(b1));
}
static __device__ __forceinline__ unsigned tf32_bits(float f) {
    unsigned u; asm("cvt.rna.tf32.f32 %0, %1;" : "=r"(u) : "f"(f)); return u;
}
static __device__ __forceinline__ unsigned pack_h2(float lo, float hi) {
    __half2 h = __floats2half2_rn(lo, hi);
    return *reinterpret_cast<unsigned*>(&h);
}

// ---------------- prep ----------------
__global__ void prep_kernel(const float* __restrict__ A, const float* __restrict__ edge,
                            const float* __restrict__ gcn_w, const float* __restrict__ gcn_b,
                            const float* __restrict__ bn_g, const float* __restrict__ bn_b,
                            const float* __restrict__ bn_m, const float* __restrict__ bn_v,
                            const float* __restrict__ res_w, const float* __restrict__ res_b,
                            const float* __restrict__ rbn_g, const float* __restrict__ rbn_b,
                            const float* __restrict__ rbn_m, const float* __restrict__ rbn_v) {
    int b = blockIdx.x, tid = threadIdx.x;
    if (b < 128) {
        int o = b;
        float inv1 = bn_g[o]  * rsqrtf(bn_v[o]  + 1e-5f);
        float inv2 = rbn_g[o] * rsqrtf(rbn_v[o] + 1e-5f);
        float wr = inv2 * res_w[o*64 + tid];   // k = tid       (res)
        float wg = inv1 * gcn_w[o*64 + tid];   // k = tid + 64  (gcn)
        #pragma unroll
        for (int s = 0; s < 2; s++) {
            int k = tid + s*64;
            float w = s ? wg : wr;
            int ks = k >> 4, o16 = o >> 4, orow = o & 15;
            int gidp = orow & 7, rh = orow >> 3;
            int kin = k & 15, kh = kin >> 3, tg2 = (kin & 7) >> 1, par = kin & 1;
            int idx = ((((ks*8 + o16)*32 + gidp*4 + tg2) << 2) + (rh + 2*kh)) * 2 + par;
            g_Whf[idx] = __float2half_rn(w);
        }
        if (tid == 0) {
            float sh1 = bn_b[o]  - bn_m[o]  * inv1;
            float sh2 = rbn_b[o] - rbn_m[o] * inv2;
            g_bo[o]  = sh1 + sh2 + inv2 * res_b[o];
            g_g1b[o] = inv1 * gcn_b[o];
        }
    } else if (b == 128) {
        for (int i = tid; i < 1024; i += 64) {
            int v = i >> 5, w = i & 31;
            g_Ae32[i] = (v < 25 && w < 25)
                ? __uint_as_float(tf32_bits(A[v*25 + w] * edge[v*25 + w])) : 0.f;
        }
    } else {
        if (tid < 32) {
            float s = 0.f;
            if (tid < 25)
                for (int v = 0; v < 25; v++) s += A[v*25 + tid] * edge[v*25 + tid];
            g_sumAe[tid] = s;
        }
    }
}

// ---------------- fused persistent kernel (one pipeline per CTA) ----------------
// smem floats: Wh | raw | Zh | Ae | bo | g1b | sum | scol
#define SWH_OFF  0                       // 8192
#define XBR_OFF  8192                    // 8448
#define ZH_OFF   16640                   // 8704
#define AE_OFF   25344                   // 1280
#define BO_OFF   26624
#define G1_OFF   26752
#define SUM_OFF  26880
#define SCOL_OFF 26912                   // 4 x 128
#define SMEM_FLOATS 27424                // 109,696 B -> 2 CTAs/SM

extern __shared__ float smem[];

static __device__ __forceinline__ void issue_tile(const float* __restrict__ x,
                                                  float* __restrict__ raw, int t, int tid) {
    int n = t / 60, mt = t - n * 60;
    int m0a = (mt * 125) & ~3;           // 16B-aligned, m0a+128 <= 7500
    const float* src = x + (size_t)n * 64 * MTOT + m0a;
    #pragma unroll
    for (int j = 0; j < 8; j++) {
        int i = tid + 256 * j;           // < 2048 float4 chunks
        int c = i >> 5, q = (i & 31) * 4;
        const float* g = src + (size_t)c * MTOT + q;
        unsigned sa = (unsigned)__cvta_generic_to_shared(raw + c * RS + q);
        asm volatile("cp.async.cg.shared.global [%0], [%1], 16;\n" :: "r"(sa), "l"(g));
    }
}

__global__ __launch_bounds__(256, 2) void fused_kernel(const float* __restrict__ x,
                                                       float* __restrict__ out) {
    int tid = threadIdx.x, lane = tid & 31, wid = tid >> 5;  // 8 warps
    int gid = lane >> 2, tig = lane & 3;
    int ow = wid & 3, mw = wid >> 2;     // 4 o-warps x 2 m-warps
    int ob = ow * 32, mb = mw * 64;

    float*    xbr = smem + XBR_OFF;
    unsigned* zhU = reinterpret_cast<unsigned*>(smem + ZH_OFF);
    __half*   zhH = reinterpret_cast<__half*>(smem + ZH_OFF);
    float*    sAe = smem + AE_OFF;
    unsigned* sAeU = reinterpret_cast<unsigned*>(sAe);

    // ---- one-time init ----
    for (int i = tid; i < 2048; i += 256)   // W frags (32KB)
        *reinterpret_cast<uint4*>(&smem[SWH_OFF + i*4]) =
            reinterpret_cast<const uint4*>(g_Whf)[i];
    for (int i = tid; i < 1024; i += 256)
        sAe[(i >> 5) * AS + (i & 31)] = g_Ae32[i];
    if (tid < 128) { smem[BO_OFF + tid] = g_bo[tid]; smem[G1_OFF + tid] = g_g1b[tid]; }
    if (tid < 32)  { smem[SUM_OFF + tid] = g_sumAe[tid]; }
    for (int i = tid; i < 512; i += 256) {  // scol[d][sc] = sumAe[(sc-d) mod 25]
        int d = i >> 7, sc = i & 127;
        int w = sc - d; w %= 25; if (w < 0) w += 25;
        smem[SCOL_OFF + i] = g_sumAe[w];
    }
    for (int j = tid; j < 256; j += 256)    // raw pad cols 128..131 = 0 (stage-1 reads)
        smem[XBR_OFF + (j >> 2) * RS + 128 + (j & 3)] = 0.f;
    for (int j = tid; j < 512; j += 256)    // Zh pad word-cols 128..135 = 0
        zhU[(j >> 3) * ZS + 128 + (j & 7)] = 0u;
    __syncthreads();

    int t = blockIdx.x, tstep = gridDim.x;
    if (t < NTILES) issue_tile(x, xbr, t, tid);
    asm volatile("cp.async.commit_group;");

    for (; t < NTILES; t += tstep) {
        int n = t / 60, mt = t - n * 60;
        int m0 = mt * 125;
        int dlt = m0 & 3;

        asm volatile("cp.async.wait_group 0;");
        __syncthreads();                     // raw ready; prev tile's Zh reads done

        // ---- convert: raw fp32 rows (2kw,2kw+1) -> half2 Zh[kw][m], kw 0..31 ----
        #pragma unroll
        for (int it = 0; it < 4; it++) {
            int i = tid + 256 * it;          // < 1024
            int kw = i >> 5, q = (i & 31) * 4;
            float4 e  = *reinterpret_cast<float4*>(&xbr[(2*kw    ) * RS + q]);
            float4 o4 = *reinterpret_cast<float4*>(&xbr[(2*kw + 1) * RS + q]);
            uint4 r;
            r.x = pack_h2(e.x, o4.x); r.y = pack_h2(e.y, o4.y);
            r.z = pack_h2(e.z, o4.z); r.w = pack_h2(e.w, o4.w);
            *reinterpret_cast<uint4*>(&zhU[kw * ZS + q]) = r;
        }

        // ---- stage 1: xA = x @ Ae (tf32 mma on raw), fp16 out -> Zh kw 32..63 ----
        for (int u = wid; u < 20; u += 8) {
            int tg = u >> 2, m16 = u & 3;
            int r0 = m16 * 16 + gid;         // channel rows r0, r0+8
            float a1[4][4];
            #pragma unroll
            for (int nt = 0; nt < 4; nt++)
                #pragma unroll
                for (int q = 0; q < 4; q++) a1[nt][q] = 0.f;
            #pragma unroll
            for (int k8 = 0; k8 < 4; k8++) {
                int cb = tg * 25 + dlt + k8 * 8;
                int c0 = min(cb + tig, 131), c1 = min(cb + tig + 4, 131);
                unsigned a[4];
                a[0] = __float_as_uint(xbr[ r0      * RS + c0]);
                a[1] = __float_as_uint(xbr[(r0 + 8) * RS + c0]);
                a[2] = __float_as_uint(xbr[ r0      * RS + c1]);
                a[3] = __float_as_uint(xbr[(r0 + 8) * RS + c1]);
                #pragma unroll
                for (int nt = 0; nt < 4; nt++) {
                    unsigned b[2];
                    b[0] = sAeU[(k8*8 + tig    ) * AS + nt*8 + gid];
                    b[1] = sAeU[(k8*8 + tig + 4) * AS + nt*8 + gid];
                    mma_tf32(a1[nt], a, b);
                }
            }
            int colb = tg * 25 + dlt;
            int kwA = 32 + (r0 >> 1),       parA = r0 & 1;
            int kwB = 32 + ((r0 + 8) >> 1), parB = (r0 + 8) & 1;
            #pragma unroll
            for (int nt = 0; nt < 4; nt++) {
                int w0 = nt * 8 + tig * 2;
                if (w0 < 25) {
                    zhH[(kwA * ZS + colb + w0) * 2 + parA] = __float2half_rn(a1[nt][0]);
                    zhH[(kwB * ZS + colb + w0) * 2 + parB] = __float2half_rn(a1[nt][2]);
                }
                if (w0 + 1 < 25) {
                    zhH[(kwA * ZS + colb + w0 + 1) * 2 + parA] = __float2half_rn(a1[nt][1]);
                    zhH[(kwB * ZS + colb + w0 + 1) * 2 + parB] = __float2half_rn(a1[nt][3]);
                }
            }
        }
        __syncthreads();                     // Zh complete; raw free

        // ---- next tile's x load overlaps main MMA + epilogue ----
        int tn = t + tstep;
        if (tn < NTILES) issue_tile(x, xbr, tn, tid);
        asm volatile("cp.async.commit_group;");

        // ---- main MMA: warp tile 32o x 64m, 8 k16-steps ----
        float acc[2][8][4];
        #pragma unroll
        for (int i = 0; i < 2; i++)
            #pragma unroll
            for (int j = 0; j < 8; j++)
                #pragma unroll
                for (int q = 0; q < 4; q++) acc[i][j][q] = 0.f;

        #pragma unroll
        for (int s = 0; s < 8; s++) {
            unsigned a[2][4];
            #pragma unroll
            for (int os = 0; os < 2; os++) {
                int o16 = ow * 2 + os;
                uint4 av = *reinterpret_cast<uint4*>(
                    &smem[SWH_OFF + (((s*8 + o16)*32 + lane) << 2)]);
                a[os][0] = av.x; a[os][1] = av.y; a[os][2] = av.z; a[os][3] = av.w;
            }
            #pragma unroll
            for (int ms = 0; ms < 8; ms++) {
                int col = mb + ms * 8 + gid + dlt;
                unsigned b0 = zhU[(s*8     + tig) * ZS + col];
                unsigned b1 = zhU[(s*8 + 4 + tig) * ZS + col];
                mma_f16(acc[0][ms], a[0], b0, b1);
                mma_f16(acc[1][ms], a[1], b0, b1);
            }
        }

        // ---- epilogue: bias via scol table + relu + store ----
        const float* scd = smem + SCOL_OFF + dlt * 128;
        bool vec_ok = ((m0 & 1) == 0);
        #pragma unroll
        for (int os = 0; os < 2; os++) {
            int r0 = ob + os * 16 + gid;
            float bo0 = smem[BO_OFF + r0],     g0 = smem[G1_OFF + r0];
            float bo1 = smem[BO_OFF + r0 + 8], g1 = smem[G1_OFF + r0 + 8];
            size_t base0 = ((size_t)n * 128 + r0) * MTOT + m0;
            size_t base1 = base0 + (size_t)8 * MTOT;
            #pragma unroll
            for (int ms = 0; ms < 8; ms++) {
                int sc = mb + ms * 8 + tig * 2;
                if (sc >= 125) continue;
                float s0 = scd[sc], s1 = scd[sc + 1];
                float v00 = fmaxf(fmaf(g0, s0, acc[os][ms][0] + bo0), 0.f);
                float v01 = fmaxf(fmaf(g0, s1, acc[os][ms][1] + bo0), 0.f);
                float v10 = fmaxf(fmaf(g1, s0, acc[os][ms][2] + bo1), 0.f);
                float v11 = fmaxf(fmaf(g1, s1, acc[os][ms][3] + bo1), 0.f);
                if (vec_ok && sc + 2 <= 125) {
                    *reinterpret_cast<float2*>(&out[base0 + sc]) = make_float2(v00, v01);
                    *reinterpret_cast<float2*>(&out[base1 + sc]) = make_float2(v10, v11);
                } else {
                    out[base0 + sc] = v00;
                    out[base1 + sc] = v10;
                    if (sc + 1 < 125) {
                        out[base0 + sc + 1] = v01;
                        out[base1 + sc + 1] = v11;
                    }
                }
            }
        }
    }
}

extern "C" void kernel_launch(void* const* d_in, const int* in_sizes, int n_in,
                              void* d_out, int out_size) {
    const float* x     = (const float*)d_in[0];
    const float* A     = (const float*)d_in[1];
    const float* edge  = (const float*)d_in[2];
    const float* gcn_w = (const float*)d_in[3];
    const float* gcn_b = (const float*)d_in[4];
    const float* bn_g  = (const float*)d_in[5];
    const float* bn_b  = (const float*)d_in[6];
    const float* bn_m  = (const float*)d_in[7];
    const float* bn_v  = (const float*)d_in[8];
    const float* res_w = (const float*)d_in[9];
    const float* res_b = (const float*)d_in[10];
    const float* rbn_g = (const float*)d_in[11];
    const float* rbn_b = (const float*)d_in[12];
    const float* rbn_m = (const float*)d_in[13];
    const float* rbn_v = (const float*)d_in[14];
    float* out = (float*)d_out;

    cudaFuncSetAttribute(fused_kernel, cudaFuncAttributeMaxDynamicSharedMemorySize,
                         SMEM_FLOATS * 4);

    prep_kernel<<<130, 64>>>(A, edge, gcn_w, gcn_b, bn_g, bn_b, bn_m, bn_v,
                             res_w, res_b, rbn_g, rbn_b, rbn_m, rbn_v);
    fused_kernel<<<296, 256, SMEM_FLOATS * 4>>>(x, out);
}

// round 15
// speedup vs baseline: 1.2307x; 1.2307x over previous
#include <cuda_runtime.h>
#include <cuda_fp16.h>

// SpatialGraphConv fused (fp16 mma.m16n8k16 main GEMM, fp32 accum).
// out[n,o,m] = relu( sum_c W[o,c]*Z[c,m] + bo[o] + g1b[o]*sumAe[m%25] )
//   Z rows 0..63  = x (res branch), rows 64..127 = xA = x@Ae (gcn branch)
// N=64 Cin=64 Cout=128 T=300 V=25, m in [0,7500). Tiles: 125 m-cols x 128 o.
// 148 CTAs x 512 thr = 2 groups of 8 warps (named-barrier pipelines, R11 shape).
// Z held as QWORD image [r=s*4+tig][col] : low word = b0, high = b1 of the
// fp16 B-frag -> 1 LDS.64 per (s,ms). W pre-baked in A-frag order (LDS.128).
// Stage-1 xA via tf32 mma on raw fp32. scol bias table in epilogue.

#define NTILES (64*60)
#define MTOT   7500
#define RS     132      // raw x row stride (floats)
#define QS     132      // Zq row stride (qwords; word-stride 264 % 32 == 8)
#define AS     40       // Ae row stride

__device__ __align__(16) __half g_Whf[16384];  // fp16 W in m16n8k16 A-frag order
__device__ float g_bo[128];
__device__ float g_g1b[128];
__device__ float g_Ae32[1024];                 // tf32 bits, zero-padded 32x32
__device__ float g_sumAe[32];

static __device__ __forceinline__ void mma_tf32(float* c, const unsigned* a, const unsigned* b) {
    asm volatile(
        "mma.sync.aligned.m16n8k8.row.col.f32.tf32.tf32.f32 "
        "{%0,%1,%2,%3}, {%4,%5,%6,%7}, {%8,%9}, {%0,%1,%2,%3};"
        : "+f"(c[0]), "+f"(c[1]), "+f"(c[2]), "+f"(c[3])
        : "r"(a[0]), "r"(a[1]), "r"(a[2]), "r"(a[3]), "r"(b[0]), "r"(b[1]));
}
static __device__ __forceinline__ void mma_f16(float* c, const unsigned* a,
                                               unsigned b0, unsigned b1) {
    asm volatile(
        "mma.sync.aligned.m16n8k16.row.col.f32.f16.f16.f32 "
        "{%0,%1,%2,%3}, {%4,%5,%6,%7}, {%8,%9}, {%0,%1,%2,%3};"
        : "+f"(c[0]), "+f"(c[1]), "+f"(c[2]), "+f"(c[3])
        : "r"(a[0]), "r"(a[1]), "r"(a[2]), "r"(a[3]), "r"(b0), "r"(b1));
}
static __device__ __forceinline__ unsigned tf32_bits(float f) {
    unsigned u; asm("cvt.rna.tf32.f32 %0, %1;" : "=r"(u) : "f"(f)); return u;
}
static __device__ __forceinline__ unsigned pack_h2(float lo, float hi) {
    __half2 h = __floats2half2_rn(lo, hi);
    return *reinterpret_cast<unsigned*>(&h);
}

#define GBAR(id) asm volatile("bar.sync %0, %1;" :: "r"(id), "r"(256) : "memory")

// ---------------- prep ----------------
__global__ void prep_kernel(const float* __restrict__ A, const float* __restrict__ edge,
                            const float* __restrict__ gcn_w, const float* __restrict__ gcn_b,
                            const float* __restrict__ bn_g, const float* __restrict__ bn_b,
                            const float* __restrict__ bn_m, const float* __restrict__ bn_v,
                            const float* __restrict__ res_w, const float* __restrict__ res_b,
                            const float* __restrict__ rbn_g, const float* __restrict__ rbn_b,
                            const float* __restrict__ rbn_m, const float* __restrict__ rbn_v) {
    int b = blockIdx.x, tid = threadIdx.x;
    if (b < 128) {
        int o = b;
        float inv1 = bn_g[o]  * rsqrtf(bn_v[o]  + 1e-5f);
        float inv2 = rbn_g[o] * rsqrtf(rbn_v[o] + 1e-5f);
        float wr = inv2 * res_w[o*64 + tid];   // k = tid       (res)
        float wg = inv1 * gcn_w[o*64 + tid];   // k = tid + 64  (gcn)
        #pragma unroll
        for (int s = 0; s < 2; s++) {
            int k = tid + s*64;
            float w = s ? wg : wr;
            int ks = k >> 4, o16 = o >> 4, orow = o & 15;
            int gidp = orow & 7, rh = orow >> 3;
            int kin = k & 15, kh = kin >> 3, tg2 = (kin & 7) >> 1, par = kin & 1;
            int idx = ((((ks*8 + o16)*32 + gidp*4 + tg2) << 2) + (rh + 2*kh)) * 2 + par;
            g_Whf[idx] = __float2half_rn(w);
        }
        if (tid == 0) {
            float sh1 = bn_b[o]  - bn_m[o]  * inv1;
            float sh2 = rbn_b[o] - rbn_m[o] * inv2;
            g_bo[o]  = sh1 + sh2 + inv2 * res_b[o];
            g_g1b[o] = inv1 * gcn_b[o];
        }
    } else if (b == 128) {
        for (int i = tid; i < 1024; i += 64) {
            int v = i >> 5, w = i & 31;
            g_Ae32[i] = (v < 25 && w < 25)
                ? __uint_as_float(tf32_bits(A[v*25 + w] * edge[v*25 + w])) : 0.f;
        }
    } else {
        if (tid < 32) {
            float s = 0.f;
            if (tid < 25)
                for (int v = 0; v < 25; v++) s += A[v*25 + tid] * edge[v*25 + tid];
            g_sumAe[tid] = s;
        }
    }
}

// ---------------- fused persistent kernel ----------------
// smem floats: Wh | (raw,Zq) g0 | (raw,Zq) g1 | Ae | bo | g1b | sum | scol
#define SWH_OFF  0                          // 8192
#define XBR_OFF(g) (8192 + (g)*16896)       // raw 64*132 = 8448 floats
#define ZQ_OFF(g)  (8192 + (g)*16896 + 8448)// Zq 32*132 qwords = 8448 floats
#define AE_OFF   41984
#define BO_OFF   (AE_OFF + 32*AS)           // 43264
#define G1_OFF   (BO_OFF + 128)
#define SUM_OFF  (G1_OFF + 128)
#define SCOL_OFF (SUM_OFF + 32)             // 4 x 128
#define SMEM_FLOATS (SCOL_OFF + 512)        // 44064 -> 176256 B

extern __shared__ float smem[];

static __device__ __forceinline__ void issue_tile(const float* __restrict__ x,
                                                  float* __restrict__ raw, int t, int gtid) {
    int n = t / 60, mt = t - n * 60;
    int m0a = (mt * 125) & ~3;              // 16B-aligned, m0a+128 <= 7500
    const float* src = x + (size_t)n * 64 * MTOT + m0a;
    #pragma unroll
    for (int j = 0; j < 8; j++) {
        int i = gtid + 256 * j;             // < 2048 float4 chunks
        int c = i >> 5, q = (i & 31) * 4;
        const float* g = src + (size_t)c * MTOT + q;
        unsigned sa = (unsigned)__cvta_generic_to_shared(raw + c * RS + q);
        asm volatile("cp.async.cg.shared.global [%0], [%1], 16;\n" :: "r"(sa), "l"(g));
    }
}

__global__ __launch_bounds__(512, 1) void fused_kernel(const float* __restrict__ x,
                                                       float* __restrict__ out) {
    int tid = threadIdx.x, lane = tid & 31, wid = tid >> 5;
    int grp = wid >> 3, gwid = wid & 7, gtid = tid & 255;
    int bar = grp + 1;
    int gid = lane >> 2, tig = lane & 3;
    int ow = gwid & 3, mw = gwid >> 2;      // 4 o-warps x 2 m-warps
    int ob = ow * 32, mb = mw * 64;

    float*    xbr = smem + XBR_OFF(grp);
    unsigned* zqW = reinterpret_cast<unsigned*>(smem + ZQ_OFF(grp));
    __half*   zqH = reinterpret_cast<__half*>(smem + ZQ_OFF(grp));
    float*    sAe = smem + AE_OFF;
    unsigned* sAeU = reinterpret_cast<unsigned*>(sAe);

    // ---- one-time init ----
    for (int i = tid; i < 2048; i += 512)   // W frags (32KB)
        *reinterpret_cast<uint4*>(&smem[SWH_OFF + i*4]) =
            reinterpret_cast<const uint4*>(g_Whf)[i];
    for (int i = tid; i < 1024; i += 512)
        sAe[(i >> 5) * AS + (i & 31)] = g_Ae32[i];
    if (tid < 128) { smem[BO_OFF + tid] = g_bo[tid]; smem[G1_OFF + tid] = g_g1b[tid]; }
    if (tid < 32)  { smem[SUM_OFF + tid] = g_sumAe[tid]; }
    for (int i = tid; i < 512; i += 512) { (void)i; }
    for (int i = tid; i < 512; i += 512) {
        int d = i >> 7, sc = i & 127;       // scol[d][sc] = sumAe[(sc-d) mod 25]
        int w = sc - d; w %= 25; if (w < 0) w += 25;
        smem[SCOL_OFF + i] = g_sumAe[w];
    }
    for (int j = tid; j < 256; j += 512) {  // raw pad cols 128..131 = 0, both groups
        int g = j >> 7, jj = j & 127;
        smem[XBR_OFF(g) + (jj >> 2) * RS + 128 + (jj & 3)] = 0.f;
    }
    for (int j = tid; j < 256; j += 512) {  // Zq pad qword cols 128..131 = 0
        int g = j >> 7, jj = j & 127;
        int r = jj >> 2, qc = 128 + (jj & 3);
        unsigned* zp = reinterpret_cast<unsigned*>(smem + ZQ_OFF(g));
        zp[(r * QS + qc) * 2]     = 0u;
        zp[(r * QS + qc) * 2 + 1] = 0u;
    }
    __syncthreads();

    int t = blockIdx.x * 2 + grp;
    int tstep = gridDim.x * 2;
    if (t < NTILES) issue_tile(x, xbr, t, gtid);
    asm volatile("cp.async.commit_group;");

    for (; t < NTILES; t += tstep) {
        int n = t / 60, mt = t - n * 60;
        int m0 = mt * 125;
        int dlt = m0 & 3;

        asm volatile("cp.async.wait_group 0;");
        GBAR(bar);                           // raw ready; prev Zq reads done

        // ---- convert: raw fp32 -> Zq qword image, rows 0..15 (x part) ----
        // unit (r, c2): qwords for cols 2c2, 2c2+1 of row r = s*4+tg
        //   low  = h2(x[16s+2tg][c], x[16s+2tg+1][c])   (b0)
        //   high = h2(x[16s+2tg+8][c], x[16s+2tg+9][c]) (b1)
        #pragma unroll
        for (int it = 0; it < 4; it++) {
            int u = gtid + 256 * it;         // < 1024
            int r = u >> 6, c2 = u & 63;
            int R0 = ((r >> 2) << 4) + ((r & 3) << 1);
            int cw = c2 * 2;
            float2 va = *reinterpret_cast<float2*>(&xbr[(R0    ) * RS + cw]);
            float2 vb = *reinterpret_cast<float2*>(&xbr[(R0 + 1) * RS + cw]);
            float2 vc = *reinterpret_cast<float2*>(&xbr[(R0 + 8) * RS + cw]);
            float2 vd = *reinterpret_cast<float2*>(&xbr[(R0 + 9) * RS + cw]);
            uint4 w;
            w.x = pack_h2(va.x, vb.x); w.y = pack_h2(vc.x, vd.x);
            w.z = pack_h2(va.y, vb.y); w.w = pack_h2(vc.y, vd.y);
            *reinterpret_cast<uint4*>(&zqW[(r * QS + cw) * 2]) = w;
        }

        // ---- stage 1: xA = x @ Ae (tf32 mma on raw), fp16 -> Zq rows 16..31 ----
        for (int u = gwid; u < 20; u += 8) {
            int tg = u >> 2, m16 = u & 3;
            int r0 = m16 * 16 + gid;         // xA rows r0, r0+8
            float a1[4][4];
            #pragma unroll
            for (int nt = 0; nt < 4; nt++)
                #pragma unroll
                for (int q = 0; q < 4; q++) a1[nt][q] = 0.f;
            #pragma unroll
            for (int k8 = 0; k8 < 4; k8++) {
                int cb = tg * 25 + dlt + k8 * 8;
                int c0 = min(cb + tig, 131), c1 = min(cb + tig + 4, 131);
                unsigned a[4];
                a[0] = __float_as_uint(xbr[ r0      * RS + c0]);
                a[1] = __float_as_uint(xbr[(r0 + 8) * RS + c0]);
                a[2] = __float_as_uint(xbr[ r0      * RS + c1]);
                a[3] = __float_as_uint(xbr[(r0 + 8) * RS + c1]);
                #pragma unroll
                for (int nt = 0; nt < 4; nt++) {
                    unsigned b[2];
                    b[0] = sAeU[(k8*8 + tig    ) * AS + nt*8 + gid];
                    b[1] = sAeU[(k8*8 + tig + 4) * AS + nt*8 + gid];
                    mma_tf32(a1[nt], a, b);
                }
            }
            int colb = tg * 25 + dlt;
            // half-index base for xA row rr: s=4+(rr>>4), j=(rr&15)>>1, par=rr&1
            //   r = s*4 + (j&3), h = j>>2 ; idx(col) = ((r*QS+col)*2 + h)*2 + par
            int rrA = r0, rrB = r0 + 8;
            int jA = (rrA & 15) >> 1, jB = (rrB & 15) >> 1;
            int rA = (4 + (rrA >> 4)) * 4 + (jA & 3), hA = jA >> 2, pA = rrA & 1;
            int rB = (4 + (rrB >> 4)) * 4 + (jB & 3), hB = jB >> 2, pB = rrB & 1;
            #pragma unroll
            for (int nt = 0; nt < 4; nt++) {
                int w0 = nt * 8 + tig * 2;
                if (w0 < 25) {
                    zqH[((rA*QS + colb + w0)*2 + hA)*2 + pA] = __float2half_rn(a1[nt][0]);
                    zqH[((rB*QS + colb + w0)*2 + hB)*2 + pB] = __float2half_rn(a1[nt][2]);
                }
                if (w0 + 1 < 25) {
                    zqH[((rA*QS + colb + w0+1)*2 + hA)*2 + pA] = __float2half_rn(a1[nt][1]);
                    zqH[((rB*QS + colb + w0+1)*2 + hB)*2 + pB] = __float2half_rn(a1[nt][3]);
                }
            }
        }
        GBAR(bar);                           // Zq complete; raw free

        // ---- next tile's x load overlaps main MMA + epilogue ----
        int tn = t + tstep;
        if (tn < NTILES) issue_tile(x, xbr, tn, gtid);
        asm volatile("cp.async.commit_group;");

        // ---- main MMA: warp tile 32o x 64m, 8 k16-steps, 1 LDS.64 per b-frag ----
        float acc[2][8][4];
        #pragma unroll
        for (int i = 0; i < 2; i++)
            #pragma unroll
            for (int j = 0; j < 8; j++)
                #pragma unroll
                for (int q = 0; q < 4; q++) acc[i][j][q] = 0.f;

        #pragma unroll
        for (int s = 0; s < 8; s++) {
            unsigned a[2][4];
            #pragma unroll
            for (int os = 0; os < 2; os++) {
                int o16 = ow * 2 + os;
                uint4 av = *reinterpret_cast<uint4*>(
                    &smem[SWH_OFF + (((s*8 + o16)*32 + lane) << 2)]);
                a[os][0] = av.x; a[os][1] = av.y; a[os][2] = av.z; a[os][3] = av.w;
            }
            int rbase = (s * 4 + tig) * QS;
            #pragma unroll
            for (int ms = 0; ms < 8; ms++) {
                int col = mb + ms * 8 + gid + dlt;
                unsigned long long bq = *reinterpret_cast<const unsigned long long*>(
                    &zqW[(rbase + col) * 2]);
                unsigned b0 = (unsigned)bq, b1 = (unsigned)(bq >> 32);
                mma_f16(acc[0][ms], a[0], b0, b1);
                mma_f16(acc[1][ms], a[1], b0, b1);
            }
        }

        // ---- epilogue: bias via scol table + relu + store ----
        const float* scd = smem + SCOL_OFF + dlt * 128;
        bool vec_ok = ((m0 & 1) == 0);
        #pragma unroll
        for (int os = 0; os < 2; os++) {
            int r0 = ob + os * 16 + gid;
            float bo0 = smem[BO_OFF + r0],     g0 = smem[G1_OFF + r0];
            float bo1 = smem[BO_OFF + r0 + 8], g1 = smem[G1_OFF + r0 + 8];
            size_t base0 = ((size_t)n * 128 + r0) * MTOT + m0;
            size_t base1 = base0 + (size_t)8 * MTOT;
            #pragma unroll
            for (int ms = 0; ms < 8; ms++) {
                int sc = mb + ms * 8 + tig * 2;
                if (sc >= 125) continue;
                float s0 = scd[sc], s1 = scd[sc + 1];
                float v00 = fmaxf(fmaf(g0, s0, acc[os][ms][0] + bo0), 0.f);
                float v01 = fmaxf(fmaf(g0, s1, acc[os][ms][1] + bo0), 0.f);
                float v10 = fmaxf(fmaf(g1, s0, acc[os][ms][2] + bo1), 0.f);
                float v11 = fmaxf(fmaf(g1, s1, acc[os][ms][3] + bo1), 0.f);
                if (vec_ok && sc + 2 <= 125) {
                    *reinterpret_cast<float2*>(&out[base0 + sc]) = make_float2(v00, v01);
                    *reinterpret_cast<float2*>(&out[base1 + sc]) = make_float2(v10, v11);
                } else {
                    out[base0 + sc] = v00;
                    out[base1 + sc] = v10;
                    if (sc + 1 < 125) {
                        out[base0 + sc + 1] = v01;
                        out[base1 + sc + 1] = v11;
                    }
                }
            }
        }
        GBAR(bar);                           // Zq reads done before next convert
    }
}

extern "C" void kernel_launch(void* const* d_in, const int* in_sizes, int n_in,
                              void* d_out, int out_size) {
    const float* x     = (const float*)d_in[0];
    const float* A     = (const float*)d_in[1];
    const float* edge  = (const float*)d_in[2];
    const float* gcn_w = (const float*)d_in[3];
    const float* gcn_b = (const float*)d_in[4];
    const float* bn_g  = (const float*)d_in[5];
    const float* bn_b  = (const float*)d_in[6];
    const float* bn_m  = (const float*)d_in[7];
    const float* bn_v  = (const float*)d_in[8];
    const float* res_w = (const float*)d_in[9];
    const float* res_b = (const float*)d_in[10];
    const float* rbn_g = (const float*)d_in[11];
    const float* rbn_b = (const float*)d_in[12];
    const float* rbn_m = (const float*)d_in[13];
    const float* rbn_v = (const float*)d_in[14];
    float* out = (float*)d_out;

    cudaFuncSetAttribute(fused_kernel, cudaFuncAttributeMaxDynamicSharedMemorySize,
                         SMEM_FLOATS * 4);

    prep_kernel<<<130, 64>>>(A, edge, gcn_w, gcn_b, bn_g, bn_b, bn_m, bn_v,
                             res_w, res_b, rbn_g, rbn_b, rbn_m, rbn_v);
    fused_kernel<<<148, 512, SMEM_FLOATS * 4>>>(x, out);
}